// round 3
// baseline (speedup 1.0000x reference)
#include <cuda_runtime.h>
#include <math.h>
#include <stdint.h>

// Problem constants (fixed by setup_inputs)
#define DIM   256
#define NHEAD 8
#define DHEAD 32
#define LQ    16320
#define PROJN 768   // [cso 256 | tso 256 | caw 128 | taw 128]

// Scratch (device globals)
__device__ float g_value[LQ * DIM];
__device__ float g_proj [LQ * PROJN];
__device__ float g_mid  [LQ * DIM];

// ---------------- TF32 tensor-core GEMM ----------------
// C = A(M x 256) * B(256 x N) + bias, row-major. Block tile 64x128, BK=32.
// 256 threads = 8 warps (2x4), warp tile 32x32 (2x4 m16n8k8 atoms).
// Smem tiles stored in MMA *fragment order*: a-frag = 1 LDS.128, b-frag = 1 LDS.64.
#define GBM 64
#define GBN 128
#define GBK 32

struct SegArgs {
    const float* B[6];
    const float* bias[6];
    int ldb[6];
    int boff[6];
};

__device__ __forceinline__ uint32_t f2tf32(float x) {
    uint32_t u;
    asm("cvt.rna.tf32.f32 %0, %1;" : "=r"(u) : "f"(x));
    return u;
}

__global__ __launch_bounds__(256) void mma_gemm(
    const float* __restrict__ A, SegArgs sa, float* __restrict__ C, int ldc)
{
    __shared__ uint32_t As[4 * 4 * 128];   // (ma,ka) atoms, 128 u32 each
    __shared__ uint32_t Bs[4 * 16 * 64];   // (ka,na) atoms, 64 u32 each

    const int tid  = threadIdx.x;
    const int bx   = blockIdx.x;
    const int bm   = blockIdx.y * GBM;
    const float* B    = sa.B[bx];
    const float* bias = sa.bias[bx];
    const int ldb  = sa.ldb[bx];
    const int boff = sa.boff[bx];
    const int cn0  = bx * GBN;

    const int lane = tid & 31, wid = tid >> 5;
    const int wm = wid >> 2, wn = wid & 3;

    float acc[2][4][4] = {};

    for (int k0 = 0; k0 < 256; k0 += GBK) {
        // ---- fill A tile 64x32 (fragment order) ----
        #pragma unroll
        for (int it = 0; it < 2; ++it) {
            int r  = (tid >> 3) + it * 32;
            int cq = (tid & 7) << 2;
            float4 v = *(const float4*)(A + (size_t)(bm + r) * 256 + k0 + cq);
            float vv[4] = {v.x, v.y, v.z, v.w};
            int ma = r >> 4, rr = r & 15;
            #pragma unroll
            for (int j = 0; j < 4; ++j) {
                int c = cq + j;
                int ka = c >> 3, cc = c & 7;
                int ln = ((rr & 7) << 2) | (cc & 3);
                int rg = (rr >> 3) | ((cc >> 2) << 1);
                As[(((ma << 2) | ka) << 7) + (ln << 2) + rg] = f2tf32(vv[j]);
            }
        }
        // ---- fill B tile 32x128 (fragment order) ----
        #pragma unroll
        for (int it = 0; it < 4; ++it) {
            int kr = (tid >> 5) + (it << 3);
            int cq = (tid & 31) << 2;
            float4 v = *(const float4*)(B + (size_t)(k0 + kr) * ldb + boff + cq);
            float vv[4] = {v.x, v.y, v.z, v.w};
            int ka = kr >> 3, kk = kr & 7;
            #pragma unroll
            for (int j = 0; j < 4; ++j) {
                int n = cq + j;
                int na = n >> 3, nn = n & 7;
                int ln = (nn << 2) | (kk & 3);
                int rg = kk >> 2;
                Bs[(((ka << 4) | na) << 6) + (ln << 1) + rg] = f2tf32(vv[j]);
            }
        }
        __syncthreads();

        #pragma unroll
        for (int ks = 0; ks < 4; ++ks) {
            uint4 af[2];
            #pragma unroll
            for (int mi = 0; mi < 2; ++mi)
                af[mi] = *(const uint4*)&As[((((wm * 2 + mi) << 2) | ks) << 7) + (lane << 2)];
            uint2 bf[4];
            #pragma unroll
            for (int ni = 0; ni < 4; ++ni)
                bf[ni] = *(const uint2*)&Bs[(((ks << 4) | (wn * 4 + ni)) << 6) + (lane << 1)];
            #pragma unroll
            for (int mi = 0; mi < 2; ++mi)
                #pragma unroll
                for (int ni = 0; ni < 4; ++ni) {
                    asm volatile(
                        "mma.sync.aligned.m16n8k8.row.col.f32.tf32.tf32.f32 "
                        "{%0,%1,%2,%3}, {%4,%5,%6,%7}, {%8,%9}, {%0,%1,%2,%3};"
                        : "+f"(acc[mi][ni][0]), "+f"(acc[mi][ni][1]),
                          "+f"(acc[mi][ni][2]), "+f"(acc[mi][ni][3])
                        : "r"(af[mi].x), "r"(af[mi].y), "r"(af[mi].z), "r"(af[mi].w),
                          "r"(bf[ni].x), "r"(bf[ni].y));
                }
        }
        __syncthreads();
    }

    // ---- epilogue ----
    const int g = lane >> 2, t = lane & 3;
    #pragma unroll
    for (int mi = 0; mi < 2; ++mi) {
        int row0 = bm + wm * 32 + mi * 16 + g;
        #pragma unroll
        for (int ni = 0; ni < 4; ++ni) {
            int lcol = wn * 32 + ni * 8 + t * 2;
            float2 bv = *(const float2*)(bias + boff + lcol);
            float2 o0, o1;
            o0.x = acc[mi][ni][0] + bv.x; o0.y = acc[mi][ni][1] + bv.y;
            o1.x = acc[mi][ni][2] + bv.x; o1.y = acc[mi][ni][3] + bv.y;
            *(float2*)(C + (size_t)row0 * ldc + cn0 + lcol) = o0;
            *(float2*)(C + (size_t)(row0 + 8) * ldc + cn0 + lcol) = o1;
        }
    }
}

// ---------------- Deformable sampling + softmax (unchanged) ----------------
__global__ __launch_bounds__(256) void deform_kernel(
    const float* __restrict__ proj,
    const float* __restrict__ value,
    const float* __restrict__ refp,
    const float* __restrict__ toff,
    float* __restrict__ mid)
{
    __shared__ float4 smw[256];
    __shared__ int4   sma[256];

    const int q    = blockIdx.x;
    const int warp = threadIdx.x >> 5;
    const int lane = threadIdx.x & 31;
    const int h = warp;
    const int l = lane >> 3;
    const int p = lane & 7;

    const int   Wl[4]  = {64, 32, 16, 8};
    const int   THl[4] = {192, 96, 48, 24};
    const int   STl[4] = {0, 12288, 15360, 16128};
    const int   Wv = Wl[l], TH = THl[l], start = STl[l];
    const float invW = 1.0f / (float)Wv, invTH = 1.0f / (float)TH;

    const float* prow = proj + (size_t)q * PROJN;

    int logit_col = (p < 4) ? (512 + h * 16 + l * 4 + p)
                            : (640 + h * 16 + l * 4 + (p - 4));
    float logit = prow[logit_col];
    float mx = logit;
    #pragma unroll
    for (int off = 16; off; off >>= 1) mx = fmaxf(mx, __shfl_xor_sync(0xffffffffu, mx, off));
    float e = __expf(logit - mx);
    float s = e;
    #pragma unroll
    for (int off = 16; off; off >>= 1) s += __shfl_xor_sync(0xffffffffu, s, off);
    float attnw = e / s;

    float rx = refp[q * 8 + l * 2 + 0];
    float ry = refp[q * 8 + l * 2 + 1];
    float ox, oy;
    if (p < 4) {
        int col = ((h * 4 + l) * 4 + p) * 2;
        ox = prow[col + 0] * invW;
        oy = prow[col + 1] * invTH;
    } else {
        int tw = (p - 4) >> 1, tp = (p - 4) & 1;
        int col = 256 + (((h * 4 + l) * 2 + tw) * 2 + tp) * 2;
        int tob = ((q * 4 + l) * 2 + tw) * 2;
        ox = toff[tob + 0] + prow[col + 0] * invW;
        oy = toff[tob + 1] + prow[col + 1] * invTH;
    }
    float x = (rx + ox) * (float)Wv - 0.5f;
    float y = (ry + oy) * (float)TH - 0.5f;

    float x0f = floorf(x), y0f = floorf(y);
    float lx = x - x0f, ly = y - y0f;
    int x0 = (int)x0f, y0 = (int)y0f;
    int x1 = x0 + 1,   y1 = y0 + 1;

    bool ix0 = (x0 >= 0) & (x0 < Wv);
    bool ix1 = (x1 >= 0) & (x1 < Wv);
    bool iy0 = (y0 >= 0) & (y0 < TH);
    bool iy1 = (y1 >= 0) & (y1 < TH);
    int cx0 = min(max(x0, 0), Wv - 1);
    int cx1 = min(max(x1, 0), Wv - 1);
    int cy0 = min(max(y0, 0), TH - 1);
    int cy1 = min(max(y1, 0), TH - 1);

    float4 w;
    w.x = attnw * (1.f - lx) * (1.f - ly) * (float)(ix0 & iy0);
    w.y = attnw * lx         * (1.f - ly) * (float)(ix1 & iy0);
    w.z = attnw * (1.f - lx) * ly         * (float)(ix0 & iy1);
    w.w = attnw * lx         * ly         * (float)(ix1 & iy1);

    const int hbase = h * DHEAD;
    int4 a;
    a.x = (start + cy0 * Wv + cx0) * DIM + hbase;
    a.y = (start + cy0 * Wv + cx1) * DIM + hbase;
    a.z = (start + cy1 * Wv + cx0) * DIM + hbase;
    a.w = (start + cy1 * Wv + cx1) * DIM + hbase;

    smw[threadIdx.x] = w;
    sma[threadIdx.x] = a;
    __syncwarp();

    float acc = 0.f;
    const int sbase = warp << 5;
    #pragma unroll 4
    for (int i = 0; i < 32; ++i) {
        float4 wi = smw[sbase + i];
        int4   ai = sma[sbase + i];
        acc += wi.x * __ldg(value + ai.x + lane);
        acc += wi.y * __ldg(value + ai.y + lane);
        acc += wi.z * __ldg(value + ai.z + lane);
        acc += wi.w * __ldg(value + ai.w + lane);
    }
    mid[(size_t)q * DIM + hbase + lane] = acc;
}

// ---------------- launch ----------------
extern "C" void kernel_launch(void* const* d_in, const int* in_sizes, int n_in,
                              void* d_out, int out_size)
{
    const float* query = (const float*)d_in[0];
    const float* refp  = (const float*)d_in[1];
    const float* toff  = (const float*)d_in[2];
    const float* inpf  = (const float*)d_in[3];
    const float* W_so  = (const float*)d_in[6];
    const float* b_so  = (const float*)d_in[7];
    const float* W_tso = (const float*)d_in[8];
    const float* b_tso = (const float*)d_in[9];
    const float* W_aw  = (const float*)d_in[10];
    const float* b_aw  = (const float*)d_in[11];
    const float* W_taw = (const float*)d_in[12];
    const float* b_taw = (const float*)d_in[13];
    const float* W_v   = (const float*)d_in[14];
    const float* b_v   = (const float*)d_in[15];
    const float* W_o   = (const float*)d_in[16];
    const float* b_o   = (const float*)d_in[17];
    float* out = (float*)d_out;

    float *value, *proj, *mid;
    cudaGetSymbolAddress((void**)&value, g_value);
    cudaGetSymbolAddress((void**)&proj,  g_proj);
    cudaGetSymbolAddress((void**)&mid,   g_mid);

    const int MB = LQ / GBM;  // 255
    dim3 blk(256);

    // value = input_flatten @ W_v + b_v   (N=256 -> 2 col blocks)
    {
        SegArgs sa{};
        sa.B[0] = W_v; sa.B[1] = W_v;
        sa.bias[0] = b_v; sa.bias[1] = b_v;
        sa.ldb[0] = 256; sa.ldb[1] = 256;
        sa.boff[0] = 0;  sa.boff[1] = 128;
        mma_gemm<<<dim3(2, MB), blk>>>(inpf, sa, value, DIM);
    }
    // fused projections: proj = query @ [W_so|W_tso|W_aw|W_taw] (N=768 -> 6 col blocks)
    {
        SegArgs sa{};
        sa.B[0] = W_so;  sa.B[1] = W_so;
        sa.B[2] = W_tso; sa.B[3] = W_tso;
        sa.B[4] = W_aw;  sa.B[5] = W_taw;
        sa.bias[0] = b_so;  sa.bias[1] = b_so;
        sa.bias[2] = b_tso; sa.bias[3] = b_tso;
        sa.bias[4] = b_aw;  sa.bias[5] = b_taw;
        sa.ldb[0] = 256; sa.ldb[1] = 256; sa.ldb[2] = 256; sa.ldb[3] = 256;
        sa.ldb[4] = 128; sa.ldb[5] = 128;
        sa.boff[0] = 0; sa.boff[1] = 128; sa.boff[2] = 0; sa.boff[3] = 128;
        sa.boff[4] = 0; sa.boff[5] = 0;
        mma_gemm<<<dim3(6, MB), blk>>>(query, sa, proj, PROJN);
    }
    // softmax + deformable bilinear sampling
    deform_kernel<<<LQ, 256>>>(proj, value, refp, toff, mid);
    // out = mid @ W_o + b_o
    {
        SegArgs sa{};
        sa.B[0] = W_o; sa.B[1] = W_o;
        sa.bias[0] = b_o; sa.bias[1] = b_o;
        sa.ldb[0] = 256; sa.ldb[1] = 256;
        sa.boff[0] = 0;  sa.boff[1] = 128;
        mma_gemm<<<dim3(2, MB), blk>>>(mid, sa, out, DIM);
    }
}

// round 4
// speedup vs baseline: 2.3635x; 2.3635x over previous
#include <cuda_runtime.h>
#include <math.h>
#include <stdint.h>

// Problem constants (fixed by setup_inputs)
#define DIM   256
#define NHEAD 8
#define DHEAD 32
#define LQ    16320
#define PROJN 768   // [cso 256 | tso 256 | caw 128 | taw 128]

// Scratch (device globals)
__device__ float g_value[LQ * DIM];
__device__ float g_proj [LQ * PROJN];
__device__ float g_mid  [LQ * DIM];

// ---------------- TF32 tensor-core GEMM v2 ----------------
// C = A(M x 256) * B(256 x N) + bias, row-major. Block tile 64x128, BK=32.
// 256 threads = 8 warps (2x4), warp tile 32x32 = 2x4 m16n8k8 atoms.
// Padded row-major smem tiles; all fragment LDS.32 are bank-conflict-free:
//   As stride 36 (=4 mod 32):  a-frag banks = g*4 + t  (32 distinct)
//   Bs stride 136 (=8 mod 32): b-frag banks = t*8 + g  (32 distinct)
#define GBM 64
#define GBN 128
#define ASTR 36
#define BSTR 136

struct SegArgs {
    const float* B[6];
    const float* bias[6];
    int ldb[6];
    int boff[6];
};

__device__ __forceinline__ uint32_t f2tf32(float x) {
    uint32_t u;
    asm("cvt.rna.tf32.f32 %0, %1;" : "=r"(u) : "f"(x));
    return u;
}
__device__ __forceinline__ uint4 q2tf32(float4 v) {
    uint4 u;
    u.x = f2tf32(v.x); u.y = f2tf32(v.y); u.z = f2tf32(v.z); u.w = f2tf32(v.w);
    return u;
}

__global__ __launch_bounds__(256) void mma_gemm(
    const float* __restrict__ A, SegArgs sa, float* __restrict__ C, int ldc)
{
    __shared__ uint32_t As[64 * ASTR];   // 9216 B
    __shared__ uint32_t Bs[32 * BSTR];   // 17408 B

    const int tid  = threadIdx.x;
    const int bx   = blockIdx.x;
    const int bm   = blockIdx.y * GBM;
    const float* B    = sa.B[bx];
    const float* bias = sa.bias[bx];
    const int ldb  = sa.ldb[bx];
    const int boff = sa.boff[bx];
    const int cn0  = bx * GBN;

    const int lane = tid & 31, wid = tid >> 5;
    const int wm = wid >> 2, wn = wid & 3;
    const int g = lane >> 2, t = lane & 3;

    // global-load pointers
    const float* Ag = A + (size_t)(bm + (tid >> 2)) * 256 + ((tid & 3) << 3);
    const float* Bg = B + (size_t)(tid >> 5) * ldb + boff + ((tid & 31) << 2);

    // smem store offsets
    const int sa_off = (tid >> 2) * ASTR + ((tid & 3) << 3);
    const int sb_off = (tid >> 5) * BSTR + ((tid & 31) << 2);

    // smem fragment-load bases
    const int abase = (wm * 32 + g) * ASTR + t;
    const int bbase = t * BSTR + wn * 32 + g;

    float acc[2][4][4] = {};

    float4 av0 = *(const float4*)(Ag);
    float4 av1 = *(const float4*)(Ag + 4);
    float4 bv[4];
    #pragma unroll
    for (int it = 0; it < 4; ++it)
        bv[it] = *(const float4*)(Bg + (size_t)(it * 8) * ldb);

    #pragma unroll
    for (int k0 = 0; k0 < 256; k0 += 32) {
        // store current slab (tf32-converted)
        *(uint4*)&As[sa_off]     = q2tf32(av0);
        *(uint4*)&As[sa_off + 4] = q2tf32(av1);
        #pragma unroll
        for (int it = 0; it < 4; ++it)
            *(uint4*)&Bs[sb_off + it * 8 * BSTR] = q2tf32(bv[it]);
        __syncthreads();

        // prefetch next slab
        if (k0 < 224) {
            av0 = *(const float4*)(Ag + k0 + 32);
            av1 = *(const float4*)(Ag + k0 + 36);
            #pragma unroll
            for (int it = 0; it < 4; ++it)
                bv[it] = *(const float4*)(Bg + (size_t)(k0 + 32 + it * 8) * ldb);
        }

        #pragma unroll
        for (int ks = 0; ks < 4; ++ks) {
            uint32_t a[2][4], b[4][2];
            #pragma unroll
            for (int mi = 0; mi < 2; ++mi) {
                int o = abase + mi * (16 * ASTR) + ks * 8;
                a[mi][0] = As[o];
                a[mi][1] = As[o + 8 * ASTR];
                a[mi][2] = As[o + 4];
                a[mi][3] = As[o + 8 * ASTR + 4];
            }
            #pragma unroll
            for (int ni = 0; ni < 4; ++ni) {
                int o = bbase + ks * (8 * BSTR) + ni * 8;
                b[ni][0] = Bs[o];
                b[ni][1] = Bs[o + 4 * BSTR];
            }
            #pragma unroll
            for (int mi = 0; mi < 2; ++mi)
                #pragma unroll
                for (int ni = 0; ni < 4; ++ni) {
                    asm volatile(
                        "mma.sync.aligned.m16n8k8.row.col.f32.tf32.tf32.f32 "
                        "{%0,%1,%2,%3}, {%4,%5,%6,%7}, {%8,%9}, {%0,%1,%2,%3};"
                        : "+f"(acc[mi][ni][0]), "+f"(acc[mi][ni][1]),
                          "+f"(acc[mi][ni][2]), "+f"(acc[mi][ni][3])
                        : "r"(a[mi][0]), "r"(a[mi][1]), "r"(a[mi][2]), "r"(a[mi][3]),
                          "r"(b[ni][0]), "r"(b[ni][1]));
                }
        }
        __syncthreads();
    }

    // ---- epilogue ----
    #pragma unroll
    for (int mi = 0; mi < 2; ++mi) {
        int row0 = bm + wm * 32 + mi * 16 + g;
        #pragma unroll
        for (int ni = 0; ni < 4; ++ni) {
            int lcol = wn * 32 + ni * 8 + t * 2;
            float2 bv2 = *(const float2*)(bias + boff + lcol);
            float2 o0, o1;
            o0.x = acc[mi][ni][0] + bv2.x; o0.y = acc[mi][ni][1] + bv2.y;
            o1.x = acc[mi][ni][2] + bv2.x; o1.y = acc[mi][ni][3] + bv2.y;
            *(float2*)(C + (size_t)row0 * ldc + cn0 + lcol) = o0;
            *(float2*)(C + (size_t)(row0 + 8) * ldc + cn0 + lcol) = o1;
        }
    }
}

// ---------------- Deformable sampling + softmax ----------------
__global__ __launch_bounds__(256) void deform_kernel(
    const float* __restrict__ proj,
    const float* __restrict__ value,
    const float* __restrict__ refp,
    const float* __restrict__ toff,
    float* __restrict__ mid)
{
    __shared__ float4 smw[256];
    __shared__ int4   sma[256];

    const int q    = blockIdx.x;
    const int warp = threadIdx.x >> 5;
    const int lane = threadIdx.x & 31;
    const int h = warp;
    const int l = lane >> 3;
    const int p = lane & 7;

    const int   Wl[4]  = {64, 32, 16, 8};
    const int   THl[4] = {192, 96, 48, 24};
    const int   STl[4] = {0, 12288, 15360, 16128};
    const int   Wv = Wl[l], TH = THl[l], start = STl[l];
    const float invW = 1.0f / (float)Wv, invTH = 1.0f / (float)TH;

    const float* prow = proj + (size_t)q * PROJN;

    int logit_col = (p < 4) ? (512 + h * 16 + l * 4 + p)
                            : (640 + h * 16 + l * 4 + (p - 4));
    float logit = prow[logit_col];
    float mx = logit;
    #pragma unroll
    for (int off = 16; off; off >>= 1) mx = fmaxf(mx, __shfl_xor_sync(0xffffffffu, mx, off));
    float e = __expf(logit - mx);
    float s = e;
    #pragma unroll
    for (int off = 16; off; off >>= 1) s += __shfl_xor_sync(0xffffffffu, s, off);
    float attnw = e / s;

    float rx = refp[q * 8 + l * 2 + 0];
    float ry = refp[q * 8 + l * 2 + 1];
    float ox, oy;
    if (p < 4) {
        int col = ((h * 4 + l) * 4 + p) * 2;
        ox = prow[col + 0] * invW;
        oy = prow[col + 1] * invTH;
    } else {
        int tw = (p - 4) >> 1, tp = (p - 4) & 1;
        int col = 256 + (((h * 4 + l) * 2 + tw) * 2 + tp) * 2;
        int tob = ((q * 4 + l) * 2 + tw) * 2;
        ox = toff[tob + 0] + prow[col + 0] * invW;
        oy = toff[tob + 1] + prow[col + 1] * invTH;
    }
    float x = (rx + ox) * (float)Wv - 0.5f;
    float y = (ry + oy) * (float)TH - 0.5f;

    float x0f = floorf(x), y0f = floorf(y);
    float lx = x - x0f, ly = y - y0f;
    int x0 = (int)x0f, y0 = (int)y0f;
    int x1 = x0 + 1,   y1 = y0 + 1;

    bool ix0 = (x0 >= 0) & (x0 < Wv);
    bool ix1 = (x1 >= 0) & (x1 < Wv);
    bool iy0 = (y0 >= 0) & (y0 < TH);
    bool iy1 = (y1 >= 0) & (y1 < TH);
    int cx0 = min(max(x0, 0), Wv - 1);
    int cx1 = min(max(x1, 0), Wv - 1);
    int cy0 = min(max(y0, 0), TH - 1);
    int cy1 = min(max(y1, 0), TH - 1);

    float4 w;
    w.x = attnw * (1.f - lx) * (1.f - ly) * (float)(ix0 & iy0);
    w.y = attnw * lx         * (1.f - ly) * (float)(ix1 & iy0);
    w.z = attnw * (1.f - lx) * ly         * (float)(ix0 & iy1);
    w.w = attnw * lx         * ly         * (float)(ix1 & iy1);

    const int hbase = h * DHEAD;
    int4 a;
    a.x = (start + cy0 * Wv + cx0) * DIM + hbase;
    a.y = (start + cy0 * Wv + cx1) * DIM + hbase;
    a.z = (start + cy1 * Wv + cx0) * DIM + hbase;
    a.w = (start + cy1 * Wv + cx1) * DIM + hbase;

    smw[threadIdx.x] = w;
    sma[threadIdx.x] = a;
    __syncwarp();

    float acc = 0.f;
    const int sbase = warp << 5;
    #pragma unroll 4
    for (int i = 0; i < 32; ++i) {
        float4 wi = smw[sbase + i];
        int4   ai = sma[sbase + i];
        acc += wi.x * __ldg(value + ai.x + lane);
        acc += wi.y * __ldg(value + ai.y + lane);
        acc += wi.z * __ldg(value + ai.z + lane);
        acc += wi.w * __ldg(value + ai.w + lane);
    }
    mid[(size_t)q * DIM + hbase + lane] = acc;
}

// ---------------- launch ----------------
extern "C" void kernel_launch(void* const* d_in, const int* in_sizes, int n_in,
                              void* d_out, int out_size)
{
    const float* query = (const float*)d_in[0];
    const float* refp  = (const float*)d_in[1];
    const float* toff  = (const float*)d_in[2];
    const float* inpf  = (const float*)d_in[3];
    const float* W_so  = (const float*)d_in[6];
    const float* b_so  = (const float*)d_in[7];
    const float* W_tso = (const float*)d_in[8];
    const float* b_tso = (const float*)d_in[9];
    const float* W_aw  = (const float*)d_in[10];
    const float* b_aw  = (const float*)d_in[11];
    const float* W_taw = (const float*)d_in[12];
    const float* b_taw = (const float*)d_in[13];
    const float* W_v   = (const float*)d_in[14];
    const float* b_v   = (const float*)d_in[15];
    const float* W_o   = (const float*)d_in[16];
    const float* b_o   = (const float*)d_in[17];
    float* out = (float*)d_out;

    float *value, *proj, *mid;
    cudaGetSymbolAddress((void**)&value, g_value);
    cudaGetSymbolAddress((void**)&proj,  g_proj);
    cudaGetSymbolAddress((void**)&mid,   g_mid);

    const int MB = LQ / GBM;  // 255
    dim3 blk(256);

    // value = input_flatten @ W_v + b_v   (N=256 -> 2 col blocks)
    {
        SegArgs sa{};
        sa.B[0] = W_v; sa.B[1] = W_v;
        sa.bias[0] = b_v; sa.bias[1] = b_v;
        sa.ldb[0] = 256; sa.ldb[1] = 256;
        sa.boff[0] = 0;  sa.boff[1] = 128;
        mma_gemm<<<dim3(2, MB), blk>>>(inpf, sa, value, DIM);
    }
    // fused projections: proj = query @ [W_so|W_tso|W_aw|W_taw] (N=768 -> 6 col blocks)
    {
        SegArgs sa{};
        sa.B[0] = W_so;  sa.B[1] = W_so;
        sa.B[2] = W_tso; sa.B[3] = W_tso;
        sa.B[4] = W_aw;  sa.B[5] = W_taw;
        sa.bias[0] = b_so;  sa.bias[1] = b_so;
        sa.bias[2] = b_tso; sa.bias[3] = b_tso;
        sa.bias[4] = b_aw;  sa.bias[5] = b_taw;
        sa.ldb[0] = 256; sa.ldb[1] = 256; sa.ldb[2] = 256; sa.ldb[3] = 256;
        sa.ldb[4] = 128; sa.ldb[5] = 128;
        sa.boff[0] = 0; sa.boff[1] = 128; sa.boff[2] = 0; sa.boff[3] = 128;
        sa.boff[4] = 0; sa.boff[5] = 0;
        mma_gemm<<<dim3(6, MB), blk>>>(query, sa, proj, PROJN);
    }
    // softmax + deformable bilinear sampling
    deform_kernel<<<LQ, 256>>>(proj, value, refp, toff, mid);
    // out = mid @ W_o + b_o
    {
        SegArgs sa{};
        sa.B[0] = W_o; sa.B[1] = W_o;
        sa.bias[0] = b_o; sa.bias[1] = b_o;
        sa.ldb[0] = 256; sa.ldb[1] = 256;
        sa.boff[0] = 0;  sa.boff[1] = 128;
        mma_gemm<<<dim3(2, MB), blk>>>(mid, sa, out, DIM);
    }
}

// round 5
// speedup vs baseline: 2.5299x; 1.0704x over previous
#include <cuda_runtime.h>
#include <cuda_fp16.h>
#include <math.h>
#include <stdint.h>

// Problem constants (fixed by setup_inputs)
#define DIM   256
#define NHEAD 8
#define DHEAD 32
#define LQ    16320
#define PROJN 768   // [cso 256 | tso 256 | caw 128 | taw 128]

// Scratch (device globals)
__device__ __half g_value[LQ * DIM];
__device__ float  g_proj [LQ * PROJN];
__device__ float  g_mid  [LQ * DIM];

// ---------------- TF32 tensor-core GEMM (templated output) ----------------
// C = A(M x 256) * B(256 x N) + bias, row-major. Block tile 64x128, BK=32.
// 256 threads = 8 warps (2x4), warp tile 32x32 = 2x4 m16n8k8 atoms.
// Padded row-major smem tiles; all fragment LDS.32 are bank-conflict-free.
#define GBM 64
#define GBN 128
#define ASTR 36
#define BSTR 136

struct SegArgs {
    const float* B[6];
    const float* bias[6];
    int ldb[6];
    int boff[6];
};

__device__ __forceinline__ uint32_t f2tf32(float x) {
    uint32_t u;
    asm("cvt.rna.tf32.f32 %0, %1;" : "=r"(u) : "f"(x));
    return u;
}
__device__ __forceinline__ uint4 q2tf32(float4 v) {
    uint4 u;
    u.x = f2tf32(v.x); u.y = f2tf32(v.y); u.z = f2tf32(v.z); u.w = f2tf32(v.w);
    return u;
}

template <typename OT>
__global__ __launch_bounds__(256) void mma_gemm(
    const float* __restrict__ A, SegArgs sa, OT* __restrict__ C, int ldc)
{
    __shared__ uint32_t As[64 * ASTR];
    __shared__ uint32_t Bs[32 * BSTR];

    const int tid  = threadIdx.x;
    const int bx   = blockIdx.x;
    const int bm   = blockIdx.y * GBM;
    const float* B    = sa.B[bx];
    const float* bias = sa.bias[bx];
    const int ldb  = sa.ldb[bx];
    const int boff = sa.boff[bx];
    const int cn0  = bx * GBN;

    const int lane = tid & 31, wid = tid >> 5;
    const int wm = wid >> 2, wn = wid & 3;
    const int g = lane >> 2, t = lane & 3;

    const float* Ag = A + (size_t)(bm + (tid >> 2)) * 256 + ((tid & 3) << 3);
    const float* Bg = B + (size_t)(tid >> 5) * ldb + boff + ((tid & 31) << 2);

    const int sa_off = (tid >> 2) * ASTR + ((tid & 3) << 3);
    const int sb_off = (tid >> 5) * BSTR + ((tid & 31) << 2);

    const int abase = (wm * 32 + g) * ASTR + t;
    const int bbase = t * BSTR + wn * 32 + g;

    float acc[2][4][4] = {};

    float4 av0 = *(const float4*)(Ag);
    float4 av1 = *(const float4*)(Ag + 4);
    float4 bv[4];
    #pragma unroll
    for (int it = 0; it < 4; ++it)
        bv[it] = *(const float4*)(Bg + (size_t)(it * 8) * ldb);

    #pragma unroll
    for (int k0 = 0; k0 < 256; k0 += 32) {
        *(uint4*)&As[sa_off]     = q2tf32(av0);
        *(uint4*)&As[sa_off + 4] = q2tf32(av1);
        #pragma unroll
        for (int it = 0; it < 4; ++it)
            *(uint4*)&Bs[sb_off + it * 8 * BSTR] = q2tf32(bv[it]);
        __syncthreads();

        if (k0 < 224) {
            av0 = *(const float4*)(Ag + k0 + 32);
            av1 = *(const float4*)(Ag + k0 + 36);
            #pragma unroll
            for (int it = 0; it < 4; ++it)
                bv[it] = *(const float4*)(Bg + (size_t)(k0 + 32 + it * 8) * ldb);
        }

        #pragma unroll
        for (int ks = 0; ks < 4; ++ks) {
            uint32_t a[2][4], b[4][2];
            #pragma unroll
            for (int mi = 0; mi < 2; ++mi) {
                int o = abase + mi * (16 * ASTR) + ks * 8;
                a[mi][0] = As[o];
                a[mi][1] = As[o + 8 * ASTR];
                a[mi][2] = As[o + 4];
                a[mi][3] = As[o + 8 * ASTR + 4];
            }
            #pragma unroll
            for (int ni = 0; ni < 4; ++ni) {
                int o = bbase + ks * (8 * BSTR) + ni * 8;
                b[ni][0] = Bs[o];
                b[ni][1] = Bs[o + 4 * BSTR];
            }
            #pragma unroll
            for (int mi = 0; mi < 2; ++mi)
                #pragma unroll
                for (int ni = 0; ni < 4; ++ni) {
                    asm volatile(
                        "mma.sync.aligned.m16n8k8.row.col.f32.tf32.tf32.f32 "
                        "{%0,%1,%2,%3}, {%4,%5,%6,%7}, {%8,%9}, {%0,%1,%2,%3};"
                        : "+f"(acc[mi][ni][0]), "+f"(acc[mi][ni][1]),
                          "+f"(acc[mi][ni][2]), "+f"(acc[mi][ni][3])
                        : "r"(a[mi][0]), "r"(a[mi][1]), "r"(a[mi][2]), "r"(a[mi][3]),
                          "r"(b[ni][0]), "r"(b[ni][1]));
                }
        }
        __syncthreads();
    }

    // ---- epilogue ----
    #pragma unroll
    for (int mi = 0; mi < 2; ++mi) {
        int row0 = bm + wm * 32 + mi * 16 + g;
        #pragma unroll
        for (int ni = 0; ni < 4; ++ni) {
            int lcol = wn * 32 + ni * 8 + t * 2;
            float2 bv2 = *(const float2*)(bias + boff + lcol);
            float v00 = acc[mi][ni][0] + bv2.x, v01 = acc[mi][ni][1] + bv2.y;
            float v10 = acc[mi][ni][2] + bv2.x, v11 = acc[mi][ni][3] + bv2.y;
            if constexpr (sizeof(OT) == 4) {
                *(float2*)((float*)C + (size_t)row0 * ldc + cn0 + lcol)       = make_float2(v00, v01);
                *(float2*)((float*)C + (size_t)(row0 + 8) * ldc + cn0 + lcol) = make_float2(v10, v11);
            } else {
                *(__half2*)((__half*)C + (size_t)row0 * ldc + cn0 + lcol)       = __floats2half2_rn(v00, v01);
                *(__half2*)((__half*)C + (size_t)(row0 + 8) * ldc + cn0 + lcol) = __floats2half2_rn(v10, v11);
            }
        }
    }
}

// ---------------- Deformable sampling + softmax (fp16 value, paired corners) ----------------
__global__ __launch_bounds__(256) void deform_kernel(
    const float* __restrict__ proj,
    const __half* __restrict__ value,   // LQ x 256 (pix-major, h*32+c inner)
    const float* __restrict__ refp,
    const float* __restrict__ toff,
    float* __restrict__ mid)
{
    __shared__ float4 smw[256];
    __shared__ int4   sma[256];

    const int q    = blockIdx.x;
    const int warp = threadIdx.x >> 5;
    const int lane = threadIdx.x & 31;
    const int h = warp;
    const int l = lane >> 3;
    const int p = lane & 7;

    const int   Wl[4]  = {64, 32, 16, 8};
    const int   THl[4] = {192, 96, 48, 24};
    const int   STl[4] = {0, 12288, 15360, 16128};
    const int   Wv = Wl[l], TH = THl[l], start = STl[l];
    const float invW = 1.0f / (float)Wv, invTH = 1.0f / (float)TH;

    const float* prow = proj + (size_t)q * PROJN;

    // ---- per-lane point setup (lane = (level, point)) ----
    int logit_col = (p < 4) ? (512 + h * 16 + l * 4 + p)
                            : (640 + h * 16 + l * 4 + (p - 4));
    float logit = prow[logit_col];
    float mx = logit;
    #pragma unroll
    for (int off = 16; off; off >>= 1) mx = fmaxf(mx, __shfl_xor_sync(0xffffffffu, mx, off));
    float e = __expf(logit - mx);
    float s = e;
    #pragma unroll
    for (int off = 16; off; off >>= 1) s += __shfl_xor_sync(0xffffffffu, s, off);
    float attnw = e / s;

    float rx = refp[q * 8 + l * 2 + 0];
    float ry = refp[q * 8 + l * 2 + 1];
    float ox, oy;
    if (p < 4) {
        int col = ((h * 4 + l) * 4 + p) * 2;
        ox = prow[col + 0] * invW;
        oy = prow[col + 1] * invTH;
    } else {
        int tw = (p - 4) >> 1, tp = (p - 4) & 1;
        int col = 256 + (((h * 4 + l) * 2 + tw) * 2 + tp) * 2;
        int tob = ((q * 4 + l) * 2 + tw) * 2;
        ox = toff[tob + 0] + prow[col + 0] * invW;
        oy = toff[tob + 1] + prow[col + 1] * invTH;
    }
    float x = (rx + ox) * (float)Wv - 0.5f;
    float y = (ry + oy) * (float)TH - 0.5f;

    float x0f = floorf(x), y0f = floorf(y);
    float lx = x - x0f, ly = y - y0f;
    int x0 = (int)x0f, y0 = (int)y0f;
    int x1 = x0 + 1,   y1 = y0 + 1;

    bool ix0 = (x0 >= 0) & (x0 < Wv);
    bool ix1 = (x1 >= 0) & (x1 < Wv);
    bool iy0 = (y0 >= 0) & (y0 < TH);
    bool iy1 = (y1 >= 0) & (y1 < TH);
    int cx0 = min(max(x0, 0), Wv - 1);
    int cx1 = min(max(x1, 0), Wv - 1);
    int cy0 = min(max(y0, 0), TH - 1);
    int cy1 = min(max(y1, 0), TH - 1);

    float4 w;
    w.x = attnw * (1.f - lx) * (1.f - ly) * (float)(ix0 & iy0);   // (y0,x0)
    w.y = attnw * lx         * (1.f - ly) * (float)(ix1 & iy0);   // (y0,x1)
    w.z = attnw * (1.f - lx) * ly         * (float)(ix0 & iy1);   // (y1,x0)
    w.w = attnw * lx         * ly         * (float)(ix1 & iy1);   // (y1,x1)

    const int hbase = h * DHEAD;
    int4 a;
    a.x = (start + cy0 * Wv + cx0) * DIM + hbase;
    a.y = (start + cy0 * Wv + cx1) * DIM + hbase;
    a.z = (start + cy1 * Wv + cx0) * DIM + hbase;
    a.w = (start + cy1 * Wv + cx1) * DIM + hbase;

    smw[threadIdx.x] = w;
    sma[threadIdx.x] = a;
    __syncwarp();

    // ---- accumulate: lanes 0-15 = x-corner 0, lanes 16-31 = x-corner 1;
    //      each lane covers 2 channels via half2. ----
    const int pair = lane >> 4;           // 0: (x0 corners), 1: (x1 corners)
    const int c2   = (lane & 15) << 1;    // channel pair base
    float ax = 0.f, ay = 0.f;
    const int sbase = warp << 5;
    #pragma unroll 4
    for (int i = 0; i < 32; ++i) {
        float4 wi = smw[sbase + i];
        int4   ai = sma[sbase + i];
        int   a01 = pair ? ai.y : ai.x;   // y0 row corner
        int   a23 = pair ? ai.w : ai.z;   // y1 row corner
        float w01 = pair ? wi.y : wi.x;
        float w23 = pair ? wi.w : wi.z;
        __half2 v0 = __ldg((const __half2*)(value + a01 + c2));
        __half2 v1 = __ldg((const __half2*)(value + a23 + c2));
        float2 f0 = __half22float2(v0);
        float2 f1 = __half22float2(v1);
        ax += w01 * f0.x + w23 * f1.x;
        ay += w01 * f0.y + w23 * f1.y;
    }
    // combine the two x-corner halves
    ax += __shfl_down_sync(0xffffffffu, ax, 16);
    ay += __shfl_down_sync(0xffffffffu, ay, 16);
    if (pair == 0)
        *(float2*)(mid + (size_t)q * DIM + hbase + c2) = make_float2(ax, ay);
}

// ---------------- launch ----------------
extern "C" void kernel_launch(void* const* d_in, const int* in_sizes, int n_in,
                              void* d_out, int out_size)
{
    const float* query = (const float*)d_in[0];
    const float* refp  = (const float*)d_in[1];
    const float* toff  = (const float*)d_in[2];
    const float* inpf  = (const float*)d_in[3];
    const float* W_so  = (const float*)d_in[6];
    const float* b_so  = (const float*)d_in[7];
    const float* W_tso = (const float*)d_in[8];
    const float* b_tso = (const float*)d_in[9];
    const float* W_aw  = (const float*)d_in[10];
    const float* b_aw  = (const float*)d_in[11];
    const float* W_taw = (const float*)d_in[12];
    const float* b_taw = (const float*)d_in[13];
    const float* W_v   = (const float*)d_in[14];
    const float* b_v   = (const float*)d_in[15];
    const float* W_o   = (const float*)d_in[16];
    const float* b_o   = (const float*)d_in[17];
    float* out = (float*)d_out;

    __half* value; float *proj, *mid;
    cudaGetSymbolAddress((void**)&value, g_value);
    cudaGetSymbolAddress((void**)&proj,  g_proj);
    cudaGetSymbolAddress((void**)&mid,   g_mid);

    const int MB = LQ / GBM;  // 255
    dim3 blk(256);

    // value = fp16(input_flatten @ W_v + b_v)
    {
        SegArgs sa{};
        sa.B[0] = W_v; sa.B[1] = W_v;
        sa.bias[0] = b_v; sa.bias[1] = b_v;
        sa.ldb[0] = 256; sa.ldb[1] = 256;
        sa.boff[0] = 0;  sa.boff[1] = 128;
        mma_gemm<__half><<<dim3(2, MB), blk>>>(inpf, sa, value, DIM);
    }
    // fused projections: proj = query @ [W_so|W_tso|W_aw|W_taw]
    {
        SegArgs sa{};
        sa.B[0] = W_so;  sa.B[1] = W_so;
        sa.B[2] = W_tso; sa.B[3] = W_tso;
        sa.B[4] = W_aw;  sa.B[5] = W_taw;
        sa.bias[0] = b_so;  sa.bias[1] = b_so;
        sa.bias[2] = b_tso; sa.bias[3] = b_tso;
        sa.bias[4] = b_aw;  sa.bias[5] = b_taw;
        sa.ldb[0] = 256; sa.ldb[1] = 256; sa.ldb[2] = 256; sa.ldb[3] = 256;
        sa.ldb[4] = 128; sa.ldb[5] = 128;
        sa.boff[0] = 0; sa.boff[1] = 128; sa.boff[2] = 0; sa.boff[3] = 128;
        sa.boff[4] = 0; sa.boff[5] = 0;
        mma_gemm<float><<<dim3(6, MB), blk>>>(query, sa, proj, PROJN);
    }
    // softmax + deformable bilinear sampling
    deform_kernel<<<LQ, 256>>>(proj, value, refp, toff, mid);
    // out = mid @ W_o + b_o
    {
        SegArgs sa{};
        sa.B[0] = W_o; sa.B[1] = W_o;
        sa.bias[0] = b_o; sa.bias[1] = b_o;
        sa.ldb[0] = 256; sa.ldb[1] = 256;
        sa.boff[0] = 0;  sa.boff[1] = 128;
        mma_gemm<float><<<dim3(2, MB), blk>>>(mid, sa, out, DIM);
    }
}

// round 6
// speedup vs baseline: 2.5784x; 1.0192x over previous
#include <cuda_runtime.h>
#include <cuda_fp16.h>
#include <math.h>
#include <stdint.h>

// Problem constants (fixed by setup_inputs)
#define DIM   256
#define NHEAD 8
#define DHEAD 32
#define LQ    16320
#define PROJN 768   // [cso 256 | tso 256 | caw 128 | taw 128]

// Scratch (device globals)
__device__ __half g_value[LQ * DIM];
__device__ float  g_proj [LQ * PROJN];
__device__ float  g_mid  [LQ * DIM];

// ---------------- TF32 tensor-core GEMM, multi-segment ----------------
// Each blockIdx.x selects a segment: its own A, B, bias, C (f32 or f16 out).
// Block tile 64x128, BK=32. 256 threads = 8 warps (2x4), warp tile 32x32.
// Padded row-major smem tiles; all fragment LDS.32 bank-conflict-free.
#define GBM 64
#define GBN 128
#define ASTR 36
#define BSTR 136

struct Seg {
    const float* A;
    const float* B;
    const float* bias;
    float*  Cf;
    __half* Ch;
    int ldb, boff, ldc, cn0, ishalf;
};
struct SegArr8 { Seg s[8]; };

__device__ __forceinline__ uint32_t f2tf32(float x) {
    uint32_t u;
    asm("cvt.rna.tf32.f32 %0, %1;" : "=r"(u) : "f"(x));
    return u;
}
__device__ __forceinline__ uint4 q2tf32(float4 v) {
    uint4 u;
    u.x = f2tf32(v.x); u.y = f2tf32(v.y); u.z = f2tf32(v.z); u.w = f2tf32(v.w);
    return u;
}

__global__ __launch_bounds__(256) void mma_gemm_seg(SegArr8 sa)
{
    __shared__ uint32_t As[64 * ASTR];
    __shared__ uint32_t Bs[32 * BSTR];

    const Seg sg = sa.s[blockIdx.x];
    const int tid = threadIdx.x;
    const int bm  = blockIdx.y * GBM;

    const int lane = tid & 31, wid = tid >> 5;
    const int wm = wid >> 2, wn = wid & 3;
    const int g = lane >> 2, t = lane & 3;

    const float* Ag = sg.A + (size_t)(bm + (tid >> 2)) * 256 + ((tid & 3) << 3);
    const float* Bg = sg.B + (size_t)(tid >> 5) * sg.ldb + sg.boff + ((tid & 31) << 2);

    const int sa_off = (tid >> 2) * ASTR + ((tid & 3) << 3);
    const int sb_off = (tid >> 5) * BSTR + ((tid & 31) << 2);

    const int abase = (wm * 32 + g) * ASTR + t;
    const int bbase = t * BSTR + wn * 32 + g;

    float acc[2][4][4] = {};

    float4 av0 = *(const float4*)(Ag);
    float4 av1 = *(const float4*)(Ag + 4);
    float4 bv[4];
    #pragma unroll
    for (int it = 0; it < 4; ++it)
        bv[it] = *(const float4*)(Bg + (size_t)(it * 8) * sg.ldb);

    #pragma unroll
    for (int k0 = 0; k0 < 256; k0 += 32) {
        *(uint4*)&As[sa_off]     = q2tf32(av0);
        *(uint4*)&As[sa_off + 4] = q2tf32(av1);
        #pragma unroll
        for (int it = 0; it < 4; ++it)
            *(uint4*)&Bs[sb_off + it * 8 * BSTR] = q2tf32(bv[it]);
        __syncthreads();

        if (k0 < 224) {
            av0 = *(const float4*)(Ag + k0 + 32);
            av1 = *(const float4*)(Ag + k0 + 36);
            #pragma unroll
            for (int it = 0; it < 4; ++it)
                bv[it] = *(const float4*)(Bg + (size_t)(k0 + 32 + it * 8) * sg.ldb);
        }

        #pragma unroll
        for (int ks = 0; ks < 4; ++ks) {
            uint32_t a[2][4], b[4][2];
            #pragma unroll
            for (int mi = 0; mi < 2; ++mi) {
                int o = abase + mi * (16 * ASTR) + ks * 8;
                a[mi][0] = As[o];
                a[mi][1] = As[o + 8 * ASTR];
                a[mi][2] = As[o + 4];
                a[mi][3] = As[o + 8 * ASTR + 4];
            }
            #pragma unroll
            for (int ni = 0; ni < 4; ++ni) {
                int o = bbase + ks * (8 * BSTR) + ni * 8;
                b[ni][0] = Bs[o];
                b[ni][1] = Bs[o + 4 * BSTR];
            }
            #pragma unroll
            for (int mi = 0; mi < 2; ++mi)
                #pragma unroll
                for (int ni = 0; ni < 4; ++ni) {
                    asm volatile(
                        "mma.sync.aligned.m16n8k8.row.col.f32.tf32.tf32.f32 "
                        "{%0,%1,%2,%3}, {%4,%5,%6,%7}, {%8,%9}, {%0,%1,%2,%3};"
                        : "+f"(acc[mi][ni][0]), "+f"(acc[mi][ni][1]),
                          "+f"(acc[mi][ni][2]), "+f"(acc[mi][ni][3])
                        : "r"(a[mi][0]), "r"(a[mi][1]), "r"(a[mi][2]), "r"(a[mi][3]),
                          "r"(b[ni][0]), "r"(b[ni][1]));
                }
        }
        __syncthreads();
    }

    // ---- epilogue ----
    #pragma unroll
    for (int mi = 0; mi < 2; ++mi) {
        int row0 = bm + wm * 32 + mi * 16 + g;
        #pragma unroll
        for (int ni = 0; ni < 4; ++ni) {
            int lcol = wn * 32 + ni * 8 + t * 2;
            float2 bv2 = *(const float2*)(sg.bias + sg.boff + lcol);
            float v00 = acc[mi][ni][0] + bv2.x, v01 = acc[mi][ni][1] + bv2.y;
            float v10 = acc[mi][ni][2] + bv2.x, v11 = acc[mi][ni][3] + bv2.y;
            if (sg.ishalf) {
                *(__half2*)(sg.Ch + (size_t)row0 * sg.ldc + sg.cn0 + lcol)       = __floats2half2_rn(v00, v01);
                *(__half2*)(sg.Ch + (size_t)(row0 + 8) * sg.ldc + sg.cn0 + lcol) = __floats2half2_rn(v10, v11);
            } else {
                *(float2*)(sg.Cf + (size_t)row0 * sg.ldc + sg.cn0 + lcol)       = make_float2(v00, v01);
                *(float2*)(sg.Cf + (size_t)(row0 + 8) * sg.ldc + sg.cn0 + lcol) = make_float2(v10, v11);
            }
        }
    }
}

// ---------------- Deformable sampling + softmax (fp16 value, paired corners) ----------------
__global__ __launch_bounds__(256) void deform_kernel(
    const float* __restrict__ proj,
    const __half* __restrict__ value,   // LQ x 256 (pix-major, h*32+c inner)
    const float* __restrict__ refp,
    const float* __restrict__ toff,
    float* __restrict__ mid)
{
    __shared__ float4 smw[256];
    __shared__ int4   sma[256];

    const int q    = blockIdx.x;
    const int warp = threadIdx.x >> 5;
    const int lane = threadIdx.x & 31;
    const int h = warp;
    const int l = lane >> 3;
    const int p = lane & 7;

    const int   Wl[4]  = {64, 32, 16, 8};
    const int   THl[4] = {192, 96, 48, 24};
    const int   STl[4] = {0, 12288, 15360, 16128};
    const int   Wv = Wl[l], TH = THl[l], start = STl[l];
    const float invW = 1.0f / (float)Wv, invTH = 1.0f / (float)TH;

    const float* prow = proj + (size_t)q * PROJN;

    int logit_col = (p < 4) ? (512 + h * 16 + l * 4 + p)
                            : (640 + h * 16 + l * 4 + (p - 4));
    float logit = prow[logit_col];
    float mx = logit;
    #pragma unroll
    for (int off = 16; off; off >>= 1) mx = fmaxf(mx, __shfl_xor_sync(0xffffffffu, mx, off));
    float e = __expf(logit - mx);
    float s = e;
    #pragma unroll
    for (int off = 16; off; off >>= 1) s += __shfl_xor_sync(0xffffffffu, s, off);
    float attnw = e / s;

    float rx = refp[q * 8 + l * 2 + 0];
    float ry = refp[q * 8 + l * 2 + 1];
    float ox, oy;
    if (p < 4) {
        int col = ((h * 4 + l) * 4 + p) * 2;
        ox = prow[col + 0] * invW;
        oy = prow[col + 1] * invTH;
    } else {
        int tw = (p - 4) >> 1, tp = (p - 4) & 1;
        int col = 256 + (((h * 4 + l) * 2 + tw) * 2 + tp) * 2;
        int tob = ((q * 4 + l) * 2 + tw) * 2;
        ox = toff[tob + 0] + prow[col + 0] * invW;
        oy = toff[tob + 1] + prow[col + 1] * invTH;
    }
    float x = (rx + ox) * (float)Wv - 0.5f;
    float y = (ry + oy) * (float)TH - 0.5f;

    float x0f = floorf(x), y0f = floorf(y);
    float lx = x - x0f, ly = y - y0f;
    int x0 = (int)x0f, y0 = (int)y0f;
    int x1 = x0 + 1,   y1 = y0 + 1;

    bool ix0 = (x0 >= 0) & (x0 < Wv);
    bool ix1 = (x1 >= 0) & (x1 < Wv);
    bool iy0 = (y0 >= 0) & (y0 < TH);
    bool iy1 = (y1 >= 0) & (y1 < TH);
    int cx0 = min(max(x0, 0), Wv - 1);
    int cx1 = min(max(x1, 0), Wv - 1);
    int cy0 = min(max(y0, 0), TH - 1);
    int cy1 = min(max(y1, 0), TH - 1);

    float4 w;
    w.x = attnw * (1.f - lx) * (1.f - ly) * (float)(ix0 & iy0);   // (y0,x0)
    w.y = attnw * lx         * (1.f - ly) * (float)(ix1 & iy0);   // (y0,x1)
    w.z = attnw * (1.f - lx) * ly         * (float)(ix0 & iy1);   // (y1,x0)
    w.w = attnw * lx         * ly         * (float)(ix1 & iy1);   // (y1,x1)

    const int hbase = h * DHEAD;
    int4 a;
    a.x = (start + cy0 * Wv + cx0) * DIM + hbase;
    a.y = (start + cy0 * Wv + cx1) * DIM + hbase;
    a.z = (start + cy1 * Wv + cx0) * DIM + hbase;
    a.w = (start + cy1 * Wv + cx1) * DIM + hbase;

    smw[threadIdx.x] = w;
    sma[threadIdx.x] = a;
    __syncwarp();

    // lanes 0-15 = x-corner 0, lanes 16-31 = x-corner 1; 2 channels per lane.
    const int pair = lane >> 4;
    const int c2   = (lane & 15) << 1;
    float ax = 0.f, ay = 0.f;
    const int sbase = warp << 5;
    #pragma unroll 8
    for (int i = 0; i < 32; ++i) {
        float4 wi = smw[sbase + i];
        int4   ai = sma[sbase + i];
        int   a01 = pair ? ai.y : ai.x;
        int   a23 = pair ? ai.w : ai.z;
        float w01 = pair ? wi.y : wi.x;
        float w23 = pair ? wi.w : wi.z;
        __half2 v0 = __ldg((const __half2*)(value + a01 + c2));
        __half2 v1 = __ldg((const __half2*)(value + a23 + c2));
        float2 f0 = __half22float2(v0);
        float2 f1 = __half22float2(v1);
        ax += w01 * f0.x + w23 * f1.x;
        ay += w01 * f0.y + w23 * f1.y;
    }
    ax += __shfl_down_sync(0xffffffffu, ax, 16);
    ay += __shfl_down_sync(0xffffffffu, ay, 16);
    if (pair == 0)
        *(float2*)(mid + (size_t)q * DIM + hbase + c2) = make_float2(ax, ay);
}

// Dummy launch-phase shifter so ncu (-s 5 -c 1) captures deform_kernel.
__global__ void phase_pad_kernel() {}

// ---------------- launch ----------------
extern "C" void kernel_launch(void* const* d_in, const int* in_sizes, int n_in,
                              void* d_out, int out_size)
{
    const float* query = (const float*)d_in[0];
    const float* refp  = (const float*)d_in[1];
    const float* toff  = (const float*)d_in[2];
    const float* inpf  = (const float*)d_in[3];
    const float* W_so  = (const float*)d_in[6];
    const float* b_so  = (const float*)d_in[7];
    const float* W_tso = (const float*)d_in[8];
    const float* b_tso = (const float*)d_in[9];
    const float* W_aw  = (const float*)d_in[10];
    const float* b_aw  = (const float*)d_in[11];
    const float* W_taw = (const float*)d_in[12];
    const float* b_taw = (const float*)d_in[13];
    const float* W_v   = (const float*)d_in[14];
    const float* b_v   = (const float*)d_in[15];
    const float* W_o   = (const float*)d_in[16];
    const float* b_o   = (const float*)d_in[17];
    float* out = (float*)d_out;

    __half* value; float *proj, *mid;
    cudaGetSymbolAddress((void**)&value, g_value);
    cudaGetSymbolAddress((void**)&proj,  g_proj);
    cudaGetSymbolAddress((void**)&mid,   g_mid);

    const int MB = LQ / GBM;  // 255
    dim3 blk(256);

    // ---- fused value + projections GEMM (8 segments) ----
    {
        SegArr8 sa{};
        // value (fp16 out), N=256 -> 2 segments
        for (int i = 0; i < 2; ++i) {
            sa.s[i].A = inpf; sa.s[i].B = W_v; sa.s[i].bias = b_v;
            sa.s[i].Ch = value; sa.s[i].ldb = 256; sa.s[i].boff = i * 128;
            sa.s[i].ldc = DIM; sa.s[i].cn0 = i * 128; sa.s[i].ishalf = 1;
        }
        // cso
        for (int i = 0; i < 2; ++i) {
            sa.s[2 + i].A = query; sa.s[2 + i].B = W_so; sa.s[2 + i].bias = b_so;
            sa.s[2 + i].Cf = proj; sa.s[2 + i].ldb = 256; sa.s[2 + i].boff = i * 128;
            sa.s[2 + i].ldc = PROJN; sa.s[2 + i].cn0 = i * 128; sa.s[2 + i].ishalf = 0;
        }
        // tso
        for (int i = 0; i < 2; ++i) {
            sa.s[4 + i].A = query; sa.s[4 + i].B = W_tso; sa.s[4 + i].bias = b_tso;
            sa.s[4 + i].Cf = proj; sa.s[4 + i].ldb = 256; sa.s[4 + i].boff = i * 128;
            sa.s[4 + i].ldc = PROJN; sa.s[4 + i].cn0 = 256 + i * 128; sa.s[4 + i].ishalf = 0;
        }
        // caw
        sa.s[6].A = query; sa.s[6].B = W_aw; sa.s[6].bias = b_aw;
        sa.s[6].Cf = proj; sa.s[6].ldb = 128; sa.s[6].boff = 0;
        sa.s[6].ldc = PROJN; sa.s[6].cn0 = 512; sa.s[6].ishalf = 0;
        // taw
        sa.s[7].A = query; sa.s[7].B = W_taw; sa.s[7].bias = b_taw;
        sa.s[7].Cf = proj; sa.s[7].ldb = 128; sa.s[7].boff = 0;
        sa.s[7].ldc = PROJN; sa.s[7].cn0 = 640; sa.s[7].ishalf = 0;

        mma_gemm_seg<<<dim3(8, MB), blk>>>(sa);
    }
    // ---- softmax + deformable bilinear sampling ----
    deform_kernel<<<LQ, 256>>>(proj, value, refp, toff, mid);
    // ---- out = mid @ W_o + b_o ----
    {
        SegArr8 sa{};
        for (int i = 0; i < 2; ++i) {
            sa.s[i].A = mid; sa.s[i].B = W_o; sa.s[i].bias = b_o;
            sa.s[i].Cf = out; sa.s[i].ldb = 256; sa.s[i].boff = i * 128;
            sa.s[i].ldc = DIM; sa.s[i].cn0 = i * 128; sa.s[i].ishalf = 0;
        }
        mma_gemm_seg<<<dim3(2, MB), blk>>>(sa);
    }
    // phase pad: keeps 4 launches per call so ncu (-s 5) lands on deform_kernel
    phase_pad_kernel<<<1, 32>>>();
}

// round 7
// speedup vs baseline: 2.9536x; 1.1455x over previous
#include <cuda_runtime.h>
#include <cuda_fp16.h>
#include <math.h>
#include <stdint.h>

// Problem constants (fixed by setup_inputs)
#define DIM   256
#define NHEAD 8
#define DHEAD 32
#define LQ    16320
#define PROJN 768   // [cso 256 | tso 256 | caw 128 | taw 128]

// Scratch (device globals)
__device__ __half g_value[LQ * DIM];
__device__ float  g_proj [LQ * PROJN];
__device__ float  g_mid  [LQ * DIM];

// ---------------- TF32 tensor-core GEMM, multi-segment ----------------
#define GBM 64
#define GBN 128
#define ASTR 36
#define BSTR 136

struct Seg {
    const float* A;
    const float* B;
    const float* bias;
    float*  Cf;
    __half* Ch;
    int ldb, boff, ldc, cn0, ishalf;
};
struct SegArr { Seg s[4]; };

__device__ __forceinline__ uint32_t f2tf32(float x) {
    uint32_t u;
    asm("cvt.rna.tf32.f32 %0, %1;" : "=r"(u) : "f"(x));
    return u;
}
__device__ __forceinline__ uint4 q2tf32(float4 v) {
    uint4 u;
    u.x = f2tf32(v.x); u.y = f2tf32(v.y); u.z = f2tf32(v.z); u.w = f2tf32(v.w);
    return u;
}

__global__ __launch_bounds__(256) void mma_gemm_seg(SegArr sa)
{
    __shared__ uint32_t As[64 * ASTR];
    __shared__ uint32_t Bs[32 * BSTR];

    const Seg sg = sa.s[blockIdx.x];
    const int tid = threadIdx.x;
    const int bm  = blockIdx.y * GBM;

    const int lane = tid & 31, wid = tid >> 5;
    const int wm = wid >> 2, wn = wid & 3;
    const int g = lane >> 2, t = lane & 3;

    const float* Ag = sg.A + (size_t)(bm + (tid >> 2)) * 256 + ((tid & 3) << 3);
    const float* Bg = sg.B + (size_t)(tid >> 5) * sg.ldb + sg.boff + ((tid & 31) << 2);

    const int sa_off = (tid >> 2) * ASTR + ((tid & 3) << 3);
    const int sb_off = (tid >> 5) * BSTR + ((tid & 31) << 2);

    const int abase = (wm * 32 + g) * ASTR + t;
    const int bbase = t * BSTR + wn * 32 + g;

    float acc[2][4][4] = {};

    float4 av0 = *(const float4*)(Ag);
    float4 av1 = *(const float4*)(Ag + 4);
    float4 bv[4];
    #pragma unroll
    for (int it = 0; it < 4; ++it)
        bv[it] = *(const float4*)(Bg + (size_t)(it * 8) * sg.ldb);

    #pragma unroll
    for (int k0 = 0; k0 < 256; k0 += 32) {
        *(uint4*)&As[sa_off]     = q2tf32(av0);
        *(uint4*)&As[sa_off + 4] = q2tf32(av1);
        #pragma unroll
        for (int it = 0; it < 4; ++it)
            *(uint4*)&Bs[sb_off + it * 8 * BSTR] = q2tf32(bv[it]);
        __syncthreads();

        if (k0 < 224) {
            av0 = *(const float4*)(Ag + k0 + 32);
            av1 = *(const float4*)(Ag + k0 + 36);
            #pragma unroll
            for (int it = 0; it < 4; ++it)
                bv[it] = *(const float4*)(Bg + (size_t)(k0 + 32 + it * 8) * sg.ldb);
        }

        #pragma unroll
        for (int ks = 0; ks < 4; ++ks) {
            uint32_t a[2][4], b[4][2];
            #pragma unroll
            for (int mi = 0; mi < 2; ++mi) {
                int o = abase + mi * (16 * ASTR) + ks * 8;
                a[mi][0] = As[o];
                a[mi][1] = As[o + 8 * ASTR];
                a[mi][2] = As[o + 4];
                a[mi][3] = As[o + 8 * ASTR + 4];
            }
            #pragma unroll
            for (int ni = 0; ni < 4; ++ni) {
                int o = bbase + ks * (8 * BSTR) + ni * 8;
                b[ni][0] = Bs[o];
                b[ni][1] = Bs[o + 4 * BSTR];
            }
            #pragma unroll
            for (int mi = 0; mi < 2; ++mi)
                #pragma unroll
                for (int ni = 0; ni < 4; ++ni) {
                    asm volatile(
                        "mma.sync.aligned.m16n8k8.row.col.f32.tf32.tf32.f32 "
                        "{%0,%1,%2,%3}, {%4,%5,%6,%7}, {%8,%9}, {%0,%1,%2,%3};"
                        : "+f"(acc[mi][ni][0]), "+f"(acc[mi][ni][1]),
                          "+f"(acc[mi][ni][2]), "+f"(acc[mi][ni][3])
                        : "r"(a[mi][0]), "r"(a[mi][1]), "r"(a[mi][2]), "r"(a[mi][3]),
                          "r"(b[ni][0]), "r"(b[ni][1]));
                }
        }
        __syncthreads();
    }

    #pragma unroll
    for (int mi = 0; mi < 2; ++mi) {
        int row0 = bm + wm * 32 + mi * 16 + g;
        #pragma unroll
        for (int ni = 0; ni < 4; ++ni) {
            int lcol = wn * 32 + ni * 8 + t * 2;
            float2 bv2 = *(const float2*)(sg.bias + sg.boff + lcol);
            float v00 = acc[mi][ni][0] + bv2.x, v01 = acc[mi][ni][1] + bv2.y;
            float v10 = acc[mi][ni][2] + bv2.x, v11 = acc[mi][ni][3] + bv2.y;
            if (sg.ishalf) {
                *(__half2*)(sg.Ch + (size_t)row0 * sg.ldc + sg.cn0 + lcol)       = __floats2half2_rn(v00, v01);
                *(__half2*)(sg.Ch + (size_t)(row0 + 8) * sg.ldc + sg.cn0 + lcol) = __floats2half2_rn(v10, v11);
            } else {
                *(float2*)(sg.Cf + (size_t)row0 * sg.ldc + sg.cn0 + lcol)       = make_float2(v00, v01);
                *(float2*)(sg.Cf + (size_t)(row0 + 8) * sg.ldc + sg.cn0 + lcol) = make_float2(v10, v11);
            }
        }
    }
}

// ---------------- Deformable sampling + softmax v3 ----------------
// Setup: lane = (level, point). Accumulate: lane = (pt-parity, corner, octet);
// one LDG.128 (__ldcg, L2-only) per (point-pair, corner) covering 8 fp16 channels.
__global__ __launch_bounds__(256) void deform_kernel(
    const float* __restrict__ proj,
    const __half* __restrict__ value,   // LQ x 256 (pix-major, h*32+c inner)
    const float* __restrict__ refp,
    const float* __restrict__ toff,
    float* __restrict__ mid)
{
    __shared__ float4 smw[256];
    __shared__ int4   sma[256];

    const int q    = blockIdx.x;
    const int warp = threadIdx.x >> 5;
    const int lane = threadIdx.x & 31;
    const int h = warp;
    const int l = lane >> 3;
    const int p = lane & 7;

    const int   Wl[4]  = {64, 32, 16, 8};
    const int   THl[4] = {192, 96, 48, 24};
    const int   STl[4] = {0, 12288, 15360, 16128};
    const int   Wv = Wl[l], TH = THl[l], start = STl[l];
    const float invW = 1.0f / (float)Wv, invTH = 1.0f / (float)TH;

    const float* prow = proj + (size_t)q * PROJN;

    int logit_col = (p < 4) ? (512 + h * 16 + l * 4 + p)
                            : (640 + h * 16 + l * 4 + (p - 4));
    float logit = prow[logit_col];
    float mx = logit;
    #pragma unroll
    for (int off = 16; off; off >>= 1) mx = fmaxf(mx, __shfl_xor_sync(0xffffffffu, mx, off));
    float e = __expf(logit - mx);
    float s = e;
    #pragma unroll
    for (int off = 16; off; off >>= 1) s += __shfl_xor_sync(0xffffffffu, s, off);
    float attnw = e / s;

    float rx = refp[q * 8 + l * 2 + 0];
    float ry = refp[q * 8 + l * 2 + 1];
    float ox, oy;
    if (p < 4) {
        int col = ((h * 4 + l) * 4 + p) * 2;
        ox = prow[col + 0] * invW;
        oy = prow[col + 1] * invTH;
    } else {
        int tw = (p - 4) >> 1, tp = (p - 4) & 1;
        int col = 256 + (((h * 4 + l) * 2 + tw) * 2 + tp) * 2;
        int tob = ((q * 4 + l) * 2 + tw) * 2;
        ox = toff[tob + 0] + prow[col + 0] * invW;
        oy = toff[tob + 1] + prow[col + 1] * invTH;
    }
    float x = (rx + ox) * (float)Wv - 0.5f;
    float y = (ry + oy) * (float)TH - 0.5f;

    float x0f = floorf(x), y0f = floorf(y);
    float lx = x - x0f, ly = y - y0f;
    int x0 = (int)x0f, y0 = (int)y0f;
    int x1 = x0 + 1,   y1 = y0 + 1;

    bool ix0 = (x0 >= 0) & (x0 < Wv);
    bool ix1 = (x1 >= 0) & (x1 < Wv);
    bool iy0 = (y0 >= 0) & (y0 < TH);
    bool iy1 = (y1 >= 0) & (y1 < TH);
    int cx0 = min(max(x0, 0), Wv - 1);
    int cx1 = min(max(x1, 0), Wv - 1);
    int cy0 = min(max(y0, 0), TH - 1);
    int cy1 = min(max(y1, 0), TH - 1);

    float4 w;
    w.x = attnw * (1.f - lx) * (1.f - ly) * (float)(ix0 & iy0);   // (y0,x0)
    w.y = attnw * lx         * (1.f - ly) * (float)(ix1 & iy0);   // (y0,x1)
    w.z = attnw * (1.f - lx) * ly         * (float)(ix0 & iy1);   // (y1,x0)
    w.w = attnw * lx         * ly         * (float)(ix1 & iy1);   // (y1,x1)

    const int hbase = h * DHEAD;
    int4 a;
    a.x = (start + cy0 * Wv + cx0) * DIM + hbase;
    a.y = (start + cy0 * Wv + cx1) * DIM + hbase;
    a.z = (start + cy1 * Wv + cx0) * DIM + hbase;
    a.w = (start + cy1 * Wv + cx1) * DIM + hbase;

    smw[threadIdx.x] = w;
    sma[threadIdx.x] = a;
    __syncwarp();

    // ---- accumulation: lane = p2*16 + c*4 + o ----
    const int p2 = lane >> 4;          // point parity
    const int c  = (lane >> 2) & 3;    // corner
    const int o  = lane & 3;           // channel octet (8 halfs)
    const int ob = o << 3;

    const int* aw_i   = (const int*)sma;     // word view
    const float* aw_f = (const float*)smw;
    const int sbase4 = (warp << 5) << 2;     // word base for this warp

    float acc[8] = {};
    #pragma unroll
    for (int i = 0; i < 16; ++i) {
        int widx = sbase4 + ((i * 2 + p2) << 2) + c;
        int   addr = aw_i[widx];
        float wgt  = aw_f[widx];
        uint4 v = __ldcg((const uint4*)(value + addr + ob));
        float2 f0 = __half22float2(*(__half2*)&v.x);
        float2 f1 = __half22float2(*(__half2*)&v.y);
        float2 f2 = __half22float2(*(__half2*)&v.z);
        float2 f3 = __half22float2(*(__half2*)&v.w);
        acc[0] += wgt * f0.x; acc[1] += wgt * f0.y;
        acc[2] += wgt * f1.x; acc[3] += wgt * f1.y;
        acc[4] += wgt * f2.x; acc[5] += wgt * f2.y;
        acc[6] += wgt * f3.x; acc[7] += wgt * f3.y;
    }
    // reduce over corner (xor 4, 8) then point-parity (xor 16)
    #pragma unroll
    for (int j = 0; j < 8; ++j) {
        acc[j] += __shfl_xor_sync(0xffffffffu, acc[j], 4);
        acc[j] += __shfl_xor_sync(0xffffffffu, acc[j], 8);
        acc[j] += __shfl_xor_sync(0xffffffffu, acc[j], 16);
    }
    if (lane < 4) {
        float* dst = mid + (size_t)q * DIM + hbase + (lane << 3);
        *(float4*)(dst)     = make_float4(acc[0], acc[1], acc[2], acc[3]);
        *(float4*)(dst + 4) = make_float4(acc[4], acc[5], acc[6], acc[7]);
    }
}

// ---------------- launch ----------------
extern "C" void kernel_launch(void* const* d_in, const int* in_sizes, int n_in,
                              void* d_out, int out_size)
{
    const float* query = (const float*)d_in[0];
    const float* refp  = (const float*)d_in[1];
    const float* toff  = (const float*)d_in[2];
    const float* inpf  = (const float*)d_in[3];
    const float* W_so  = (const float*)d_in[6];
    const float* b_so  = (const float*)d_in[7];
    const float* W_tso = (const float*)d_in[8];
    const float* b_tso = (const float*)d_in[9];
    const float* W_aw  = (const float*)d_in[10];
    const float* b_aw  = (const float*)d_in[11];
    const float* W_taw = (const float*)d_in[12];
    const float* b_taw = (const float*)d_in[13];
    const float* W_v   = (const float*)d_in[14];
    const float* b_v   = (const float*)d_in[15];
    const float* W_o   = (const float*)d_in[16];
    const float* b_o   = (const float*)d_in[17];
    float* out = (float*)d_out;

    __half* value; float *proj, *mid;
    cudaGetSymbolAddress((void**)&value, g_value);
    cudaGetSymbolAddress((void**)&proj,  g_proj);
    cudaGetSymbolAddress((void**)&mid,   g_mid);

    const int MB = LQ / GBM;  // 255
    dim3 blk(256);

    // (1) value = fp16(input_flatten @ W_v + b_v)
    {
        SegArr sa{};
        for (int i = 0; i < 2; ++i) {
            sa.s[i].A = inpf; sa.s[i].B = W_v; sa.s[i].bias = b_v;
            sa.s[i].Ch = value; sa.s[i].ldb = 256; sa.s[i].boff = i * 128;
            sa.s[i].ldc = DIM; sa.s[i].cn0 = i * 128; sa.s[i].ishalf = 1;
        }
        mma_gemm_seg<<<dim3(2, MB), blk>>>(sa);
    }
    // (2) proj[0:512] = query @ [W_so | W_tso]
    {
        SegArr sa{};
        for (int i = 0; i < 2; ++i) {
            sa.s[i].A = query; sa.s[i].B = W_so; sa.s[i].bias = b_so;
            sa.s[i].Cf = proj; sa.s[i].ldb = 256; sa.s[i].boff = i * 128;
            sa.s[i].ldc = PROJN; sa.s[i].cn0 = i * 128; sa.s[i].ishalf = 0;
            sa.s[2 + i].A = query; sa.s[2 + i].B = W_tso; sa.s[2 + i].bias = b_tso;
            sa.s[2 + i].Cf = proj; sa.s[2 + i].ldb = 256; sa.s[2 + i].boff = i * 128;
            sa.s[2 + i].ldc = PROJN; sa.s[2 + i].cn0 = 256 + i * 128; sa.s[2 + i].ishalf = 0;
        }
        mma_gemm_seg<<<dim3(4, MB), blk>>>(sa);
    }
    // (3) proj[512:768] = query @ [W_aw | W_taw]
    {
        SegArr sa{};
        sa.s[0].A = query; sa.s[0].B = W_aw; sa.s[0].bias = b_aw;
        sa.s[0].Cf = proj; sa.s[0].ldb = 128; sa.s[0].boff = 0;
        sa.s[0].ldc = PROJN; sa.s[0].cn0 = 512; sa.s[0].ishalf = 0;
        sa.s[1].A = query; sa.s[1].B = W_taw; sa.s[1].bias = b_taw;
        sa.s[1].Cf = proj; sa.s[1].ldb = 128; sa.s[1].boff = 0;
        sa.s[1].ldc = PROJN; sa.s[1].cn0 = 640; sa.s[1].ishalf = 0;
        mma_gemm_seg<<<dim3(2, MB), blk>>>(sa);
    }
    // (4) deform  <- ncu captures absolute launch #4
    deform_kernel<<<LQ, 256>>>(proj, value, refp, toff, mid);
    // (5) out = mid @ W_o + b_o
    {
        SegArr sa{};
        for (int i = 0; i < 2; ++i) {
            sa.s[i].A = mid; sa.s[i].B = W_o; sa.s[i].bias = b_o;
            sa.s[i].Cf = out; sa.s[i].ldb = 256; sa.s[i].boff = i * 128;
            sa.s[i].ldc = DIM; sa.s[i].cn0 = i * 128; sa.s[i].ishalf = 0;
        }
        mma_gemm_seg<<<dim3(2, MB), blk>>>(sa);
    }
}

// round 8
// speedup vs baseline: 3.6240x; 1.2270x over previous
#include <cuda_runtime.h>
#include <cuda_fp16.h>
#include <math.h>
#include <stdint.h>

// Problem constants (fixed by setup_inputs)
#define DIM   256
#define NHEAD 8
#define DHEAD 32
#define LQ    16320
#define PROJN 768   // [cso 256 | tso 256 | caw 128 | taw 128]

// Scratch (device globals)
__device__ __half g_value[LQ * DIM];
__device__ float  g_proj [LQ * PROJN];
__device__ float  g_mid  [LQ * DIM];

// ---------------- FP16 tensor-core GEMM (m16n8k16), multi-segment ----------
// C = A(M x 256) * B(256 x N) + bias, fp32 accum. Block tile 64x128, BK=32.
// 256 threads = 8 warps (2x4), warp tile 32x32 = 2x4 m16n8k16 atoms.
// Fragments loaded with ldmatrix.x4 (A) / ldmatrix.x4.trans (B); padded
// row-major half tiles, all LDSM phases bank-conflict-free.
#define GBM 64
#define GBN 128
#define AROW 40    // halfs per A row (32 + 8 pad)  -> 20 words
#define BROW 136   // halfs per B row (128 + 8 pad) -> 68 words

struct Seg {
    const float* A;
    const float* B;
    const float* bias;
    float*  Cf;
    __half* Ch;
    int ldb, boff, ldc, cn0, ishalf;
};
struct SegArr { Seg s[8]; };

__device__ __forceinline__ uint32_t pack2(float a, float b) {
    __half2 h = __floats2half2_rn(a, b);
    return *(uint32_t*)&h;
}
__device__ __forceinline__ uint4 pack8(float4 v0, float4 v1) {
    uint4 u;
    u.x = pack2(v0.x, v0.y); u.y = pack2(v0.z, v0.w);
    u.z = pack2(v1.x, v1.y); u.w = pack2(v1.z, v1.w);
    return u;
}
__device__ __forceinline__ void ldsm4(uint32_t& r0, uint32_t& r1, uint32_t& r2, uint32_t& r3, uint32_t addr) {
    asm volatile("ldmatrix.sync.aligned.m8n8.x4.shared.b16 {%0,%1,%2,%3}, [%4];"
        : "=r"(r0), "=r"(r1), "=r"(r2), "=r"(r3) : "r"(addr));
}
__device__ __forceinline__ void ldsm4t(uint32_t& r0, uint32_t& r1, uint32_t& r2, uint32_t& r3, uint32_t addr) {
    asm volatile("ldmatrix.sync.aligned.m8n8.x4.trans.shared.b16 {%0,%1,%2,%3}, [%4];"
        : "=r"(r0), "=r"(r1), "=r"(r2), "=r"(r3) : "r"(addr));
}

__global__ __launch_bounds__(256) void mma_gemm_seg(SegArr sa)
{
    __shared__ __half As[64 * AROW];   // 5120 B
    __shared__ __half Bs[32 * BROW];   // 8704 B

    const Seg sg = sa.s[blockIdx.x];
    const int tid = threadIdx.x;
    const int bm  = blockIdx.y * GBM;

    const int lane = tid & 31, wid = tid >> 5;
    const int wm = wid >> 2, wn = wid & 3;
    const int g = lane >> 2, t = lane & 3;

    // ---- fill mappings ----
    const int ar = tid >> 2;            // A row 0..63
    const int ak = (tid & 3) << 3;      // A k-octet base 0,8,16,24
    const float* Ag = sg.A + (size_t)(bm + ar) * 256 + ak;
    uint4* As_st = (uint4*)(As + ar * AROW + ak);

    const int bk = tid >> 5;            // B k-row 0..7 (x4 iters of +8)
    const int bn = (tid & 31) << 2;     // B col quad
    const float* Bg = sg.B + (size_t)bk * sg.ldb + sg.boff + bn;
    // store addr: Bs + (bk + it*8)*BROW + bn

    // ---- ldmatrix lane addresses ----
    const uint32_t as_addr = (uint32_t)__cvta_generic_to_shared(As);
    const uint32_t bs_addr = (uint32_t)__cvta_generic_to_shared(Bs);
    const int arow = wm * 32 + (lane & 7) + ((lane >> 3) & 1) * 8;  // + mi*16
    const int acol = (lane >> 4) * 8;                                // + ks*16
    const int brow = (lane & 7) + ((lane >> 3) & 1) * 8;             // + ks*16
    const int bcol = wn * 32 + (lane >> 4) * 8;                      // + nip*16
    const uint32_t aaddr0 = as_addr + (uint32_t)((arow * AROW + acol) * 2);
    const uint32_t baddr0 = bs_addr + (uint32_t)((brow * BROW + bcol) * 2);

    float acc[2][4][4] = {};

    // prefetch slab 0
    float4 av0 = *(const float4*)(Ag);
    float4 av1 = *(const float4*)(Ag + 4);
    float4 bv[4];
    #pragma unroll
    for (int it = 0; it < 4; ++it)
        bv[it] = *(const float4*)(Bg + (size_t)(it * 8) * sg.ldb);

    #pragma unroll
    for (int k0 = 0; k0 < 256; k0 += 32) {
        // store slab (converted to half)
        *As_st = pack8(av0, av1);
        #pragma unroll
        for (int it = 0; it < 4; ++it) {
            uint2 p; p.x = pack2(bv[it].x, bv[it].y); p.y = pack2(bv[it].z, bv[it].w);
            *(uint2*)(Bs + (bk + it * 8) * BROW + bn) = p;
        }
        __syncthreads();

        // prefetch next slab
        if (k0 < 224) {
            av0 = *(const float4*)(Ag + k0 + 32);
            av1 = *(const float4*)(Ag + k0 + 36);
            #pragma unroll
            for (int it = 0; it < 4; ++it)
                bv[it] = *(const float4*)(Bg + (size_t)(k0 + 32 + it * 8) * sg.ldb);
        }

        #pragma unroll
        for (int ks = 0; ks < 2; ++ks) {   // two k16 steps per slab
            uint32_t a[2][4], b[2][4];
            #pragma unroll
            for (int mi = 0; mi < 2; ++mi)
                ldsm4(a[mi][0], a[mi][1], a[mi][2], a[mi][3],
                      aaddr0 + (uint32_t)((mi * 16 * AROW + ks * 16) * 2));
            #pragma unroll
            for (int nip = 0; nip < 2; ++nip)
                ldsm4t(b[nip][0], b[nip][1], b[nip][2], b[nip][3],
                       baddr0 + (uint32_t)((ks * 16 * BROW + nip * 16) * 2));
            #pragma unroll
            for (int mi = 0; mi < 2; ++mi)
                #pragma unroll
                for (int ni = 0; ni < 4; ++ni) {
                    uint32_t b0 = b[ni >> 1][(ni & 1) * 2];
                    uint32_t b1 = b[ni >> 1][(ni & 1) * 2 + 1];
                    asm volatile(
                        "mma.sync.aligned.m16n8k16.row.col.f32.f16.f16.f32 "
                        "{%0,%1,%2,%3}, {%4,%5,%6,%7}, {%8,%9}, {%0,%1,%2,%3};"
                        : "+f"(acc[mi][ni][0]), "+f"(acc[mi][ni][1]),
                          "+f"(acc[mi][ni][2]), "+f"(acc[mi][ni][3])
                        : "r"(a[mi][0]), "r"(a[mi][1]), "r"(a[mi][2]), "r"(a[mi][3]),
                          "r"(b0), "r"(b1));
                }
        }
        __syncthreads();
    }

    // ---- epilogue ----
    #pragma unroll
    for (int mi = 0; mi < 2; ++mi) {
        int row0 = bm + wm * 32 + mi * 16 + g;
        #pragma unroll
        for (int ni = 0; ni < 4; ++ni) {
            int lcol = wn * 32 + ni * 8 + t * 2;
            float2 bv2 = *(const float2*)(sg.bias + sg.boff + lcol);
            float v00 = acc[mi][ni][0] + bv2.x, v01 = acc[mi][ni][1] + bv2.y;
            float v10 = acc[mi][ni][2] + bv2.x, v11 = acc[mi][ni][3] + bv2.y;
            if (sg.ishalf) {
                *(__half2*)(sg.Ch + (size_t)row0 * sg.ldc + sg.cn0 + lcol)       = __floats2half2_rn(v00, v01);
                *(__half2*)(sg.Ch + (size_t)(row0 + 8) * sg.ldc + sg.cn0 + lcol) = __floats2half2_rn(v10, v11);
            } else {
                *(float2*)(sg.Cf + (size_t)row0 * sg.ldc + sg.cn0 + lcol)       = make_float2(v00, v01);
                *(float2*)(sg.Cf + (size_t)(row0 + 8) * sg.ldc + sg.cn0 + lcol) = make_float2(v10, v11);
            }
        }
    }
}

// ---------------- Deformable sampling + softmax (v3, unchanged) ----------------
__global__ __launch_bounds__(256) void deform_kernel(
    const float* __restrict__ proj,
    const __half* __restrict__ value,
    const float* __restrict__ refp,
    const float* __restrict__ toff,
    float* __restrict__ mid)
{
    __shared__ float4 smw[256];
    __shared__ int4   sma[256];

    const int q    = blockIdx.x;
    const int warp = threadIdx.x >> 5;
    const int lane = threadIdx.x & 31;
    const int h = warp;
    const int l = lane >> 3;
    const int p = lane & 7;

    const int   Wl[4]  = {64, 32, 16, 8};
    const int   THl[4] = {192, 96, 48, 24};
    const int   STl[4] = {0, 12288, 15360, 16128};
    const int   Wv = Wl[l], TH = THl[l], start = STl[l];
    const float invW = 1.0f / (float)Wv, invTH = 1.0f / (float)TH;

    const float* prow = proj + (size_t)q * PROJN;

    int logit_col = (p < 4) ? (512 + h * 16 + l * 4 + p)
                            : (640 + h * 16 + l * 4 + (p - 4));
    float logit = prow[logit_col];
    float mx = logit;
    #pragma unroll
    for (int off = 16; off; off >>= 1) mx = fmaxf(mx, __shfl_xor_sync(0xffffffffu, mx, off));
    float e = __expf(logit - mx);
    float s = e;
    #pragma unroll
    for (int off = 16; off; off >>= 1) s += __shfl_xor_sync(0xffffffffu, s, off);
    float attnw = e / s;

    float rx = refp[q * 8 + l * 2 + 0];
    float ry = refp[q * 8 + l * 2 + 1];
    float ox, oy;
    if (p < 4) {
        int col = ((h * 4 + l) * 4 + p) * 2;
        ox = prow[col + 0] * invW;
        oy = prow[col + 1] * invTH;
    } else {
        int tw = (p - 4) >> 1, tp = (p - 4) & 1;
        int col = 256 + (((h * 4 + l) * 2 + tw) * 2 + tp) * 2;
        int tob = ((q * 4 + l) * 2 + tw) * 2;
        ox = toff[tob + 0] + prow[col + 0] * invW;
        oy = toff[tob + 1] + prow[col + 1] * invTH;
    }
    float x = (rx + ox) * (float)Wv - 0.5f;
    float y = (ry + oy) * (float)TH - 0.5f;

    float x0f = floorf(x), y0f = floorf(y);
    float lx = x - x0f, ly = y - y0f;
    int x0 = (int)x0f, y0 = (int)y0f;
    int x1 = x0 + 1,   y1 = y0 + 1;

    bool ix0 = (x0 >= 0) & (x0 < Wv);
    bool ix1 = (x1 >= 0) & (x1 < Wv);
    bool iy0 = (y0 >= 0) & (y0 < TH);
    bool iy1 = (y1 >= 0) & (y1 < TH);
    int cx0 = min(max(x0, 0), Wv - 1);
    int cx1 = min(max(x1, 0), Wv - 1);
    int cy0 = min(max(y0, 0), TH - 1);
    int cy1 = min(max(y1, 0), TH - 1);

    float4 w;
    w.x = attnw * (1.f - lx) * (1.f - ly) * (float)(ix0 & iy0);
    w.y = attnw * lx         * (1.f - ly) * (float)(ix1 & iy0);
    w.z = attnw * (1.f - lx) * ly         * (float)(ix0 & iy1);
    w.w = attnw * lx         * ly         * (float)(ix1 & iy1);

    const int hbase = h * DHEAD;
    int4 a;
    a.x = (start + cy0 * Wv + cx0) * DIM + hbase;
    a.y = (start + cy0 * Wv + cx1) * DIM + hbase;
    a.z = (start + cy1 * Wv + cx0) * DIM + hbase;
    a.w = (start + cy1 * Wv + cx1) * DIM + hbase;

    smw[threadIdx.x] = w;
    sma[threadIdx.x] = a;
    __syncwarp();

    const int p2 = lane >> 4;
    const int c  = (lane >> 2) & 3;
    const int o  = lane & 3;
    const int ob = o << 3;

    const int* aw_i   = (const int*)sma;
    const float* aw_f = (const float*)smw;
    const int sbase4 = (warp << 5) << 2;

    float acc[8] = {};
    #pragma unroll
    for (int i = 0; i < 16; ++i) {
        int widx = sbase4 + ((i * 2 + p2) << 2) + c;
        int   addr = aw_i[widx];
        float wgt  = aw_f[widx];
        uint4 v = __ldcg((const uint4*)(value + addr + ob));
        float2 f0 = __half22float2(*(__half2*)&v.x);
        float2 f1 = __half22float2(*(__half2*)&v.y);
        float2 f2 = __half22float2(*(__half2*)&v.z);
        float2 f3 = __half22float2(*(__half2*)&v.w);
        acc[0] += wgt * f0.x; acc[1] += wgt * f0.y;
        acc[2] += wgt * f1.x; acc[3] += wgt * f1.y;
        acc[4] += wgt * f2.x; acc[5] += wgt * f2.y;
        acc[6] += wgt * f3.x; acc[7] += wgt * f3.y;
    }
    #pragma unroll
    for (int j = 0; j < 8; ++j) {
        acc[j] += __shfl_xor_sync(0xffffffffu, acc[j], 4);
        acc[j] += __shfl_xor_sync(0xffffffffu, acc[j], 8);
        acc[j] += __shfl_xor_sync(0xffffffffu, acc[j], 16);
    }
    if (lane < 4) {
        float* dst = mid + (size_t)q * DIM + hbase + (lane << 3);
        *(float4*)(dst)     = make_float4(acc[0], acc[1], acc[2], acc[3]);
        *(float4*)(dst + 4) = make_float4(acc[4], acc[5], acc[6], acc[7]);
    }
}

// ---------------- launch ----------------
extern "C" void kernel_launch(void* const* d_in, const int* in_sizes, int n_in,
                              void* d_out, int out_size)
{
    const float* query = (const float*)d_in[0];
    const float* refp  = (const float*)d_in[1];
    const float* toff  = (const float*)d_in[2];
    const float* inpf  = (const float*)d_in[3];
    const float* W_so  = (const float*)d_in[6];
    const float* b_so  = (const float*)d_in[7];
    const float* W_tso = (const float*)d_in[8];
    const float* b_tso = (const float*)d_in[9];
    const float* W_aw  = (const float*)d_in[10];
    const float* b_aw  = (const float*)d_in[11];
    const float* W_taw = (const float*)d_in[12];
    const float* b_taw = (const float*)d_in[13];
    const float* W_v   = (const float*)d_in[14];
    const float* b_v   = (const float*)d_in[15];
    const float* W_o   = (const float*)d_in[16];
    const float* b_o   = (const float*)d_in[17];
    float* out = (float*)d_out;

    __half* value; float *proj, *mid;
    cudaGetSymbolAddress((void**)&value, g_value);
    cudaGetSymbolAddress((void**)&proj,  g_proj);
    cudaGetSymbolAddress((void**)&mid,   g_mid);

    const int MB = LQ / GBM;  // 255
    dim3 blk(256);

    // (1) fused value + projections GEMM (8 segments)
    {
        SegArr sa{};
        for (int i = 0; i < 2; ++i) {
            sa.s[i].A = inpf; sa.s[i].B = W_v; sa.s[i].bias = b_v;
            sa.s[i].Ch = value; sa.s[i].ldb = 256; sa.s[i].boff = i * 128;
            sa.s[i].ldc = DIM; sa.s[i].cn0 = i * 128; sa.s[i].ishalf = 1;
        }
        for (int i = 0; i < 2; ++i) {
            sa.s[2 + i].A = query; sa.s[2 + i].B = W_so; sa.s[2 + i].bias = b_so;
            sa.s[2 + i].Cf = proj; sa.s[2 + i].ldb = 256; sa.s[2 + i].boff = i * 128;
            sa.s[2 + i].ldc = PROJN; sa.s[2 + i].cn0 = i * 128; sa.s[2 + i].ishalf = 0;
            sa.s[4 + i].A = query; sa.s[4 + i].B = W_tso; sa.s[4 + i].bias = b_tso;
            sa.s[4 + i].Cf = proj; sa.s[4 + i].ldb = 256; sa.s[4 + i].boff = i * 128;
            sa.s[4 + i].ldc = PROJN; sa.s[4 + i].cn0 = 256 + i * 128; sa.s[4 + i].ishalf = 0;
        }
        sa.s[6].A = query; sa.s[6].B = W_aw; sa.s[6].bias = b_aw;
        sa.s[6].Cf = proj; sa.s[6].ldb = 128; sa.s[6].boff = 0;
        sa.s[6].ldc = PROJN; sa.s[6].cn0 = 512; sa.s[6].ishalf = 0;
        sa.s[7].A = query; sa.s[7].B = W_taw; sa.s[7].bias = b_taw;
        sa.s[7].Cf = proj; sa.s[7].ldb = 128; sa.s[7].boff = 0;
        sa.s[7].ldc = PROJN; sa.s[7].cn0 = 640; sa.s[7].ishalf = 0;
        mma_gemm_seg<<<dim3(8, MB), blk>>>(sa);
    }
    // (2) deform
    deform_kernel<<<LQ, 256>>>(proj, value, refp, toff, mid);
    // (3) out = mid @ W_o + b_o   (3 launches/call -> abs #4 = call 2's GEMM)
    {
        SegArr sa{};
        for (int i = 0; i < 2; ++i) {
            sa.s[i].A = mid; sa.s[i].B = W_o; sa.s[i].bias = b_o;
            sa.s[i].Cf = out; sa.s[i].ldb = 256; sa.s[i].boff = i * 128;
            sa.s[i].ldc = DIM; sa.s[i].cn0 = i * 128; sa.s[i].ishalf = 0;
        }
        mma_gemm_seg<<<dim3(2, MB), blk>>>(sa);
    }
}